// round 14
// baseline (speedup 1.0000x reference)
#include <cuda_runtime.h>
#include <cuda_fp16.h>
#include <mma.h>
#include <math.h>
#include <cstdint>

using namespace nvcuda;

// ---------------- problem constants ----------------
#define BB   128
#define TT   256
#define TC   200
#define EE   256
#define HH   512
#define H4   2048
#define VV   50000
#define MAX_OOV 50
#define VEXT 50050
#define LPAD 50176   // padded logits row stride

#define QSTAT 12500  // stats partial range (VV/4)
#define QWR   12513  // write quarter range (ceil VEXT/4)

#define ASTR 36      // tf32 gemm smem row stride (floats)
#define NSTG 3       // tf32 gemm cp.async stages

#define NLOGIT (LPAD / 128)        // 392 logits blocks
#define NDEC   8                   // dec2 blocks (N=1024)

#define FCH 16                     // flash-attn chunk rows
#define FS_SDEC  0
#define FS_SRAW  512
#define FS_SC    (512 + 256)
#define FS_SWC   (512 + 256 + 16)
#define FS_CHUNK (512 + 256 + 32)
#define FS_TOTAL (FS_CHUNK + 2 * FCH * HH)   // 17184 floats = 68736 B

// mega dynamic smem layout (bytes)
#define MG_AS    0                         // 2*128*40 half = 20480
#define MG_WS    20480                     // 2*128*40 half = 20480
#define MG_STAGE 40960                     // 8 warps * 16*20 fp32 = 10240
#define MG_TOTAL (40960 + 10240)           // 51200

// ---------------- scratch (device globals; no allocation) ----------------
__device__ float g_dec2[BB * 1024];        // [dec | cdec] per row
__device__ float g_context[BB * HH];
__device__ float g_cctx[BB * HH];
__device__ float g_nscores[BB][TT];        // normalized cscores (attn 1)
__device__ float g_part[BB][4][2];         // per-quarter online {m, s}
__device__ __half g_logits_h[BB * LPAD];   // fp16 logits+bias (12.8 MB)

__device__ __forceinline__ float sigmoidf_(float x) {
    return 1.0f / (1.0f + __expf(-x));
}

// ---------------- cp.async helpers ----------------
__device__ __forceinline__ void cp_async16(uint32_t dst, const void* src) {
    asm volatile("cp.async.cg.shared.global [%0], [%1], 16;\n" :: "r"(dst), "l"(src));
}
__device__ __forceinline__ void cp_commit() {
    asm volatile("cp.async.commit_group;\n" ::);
}
template <int N>
__device__ __forceinline__ void cp_wait() {
    asm volatile("cp.async.wait_group %0;\n" :: "n"(N));
}

// block reduce: op 0 = max, 1 = sum (blockDim <= 1024)
__device__ __forceinline__ float block_reduce(float v, float* red, int op) {
    int lane = threadIdx.x & 31, warp = threadIdx.x >> 5;
    #pragma unroll
    for (int o = 16; o > 0; o >>= 1) {
        float u = __shfl_xor_sync(0xffffffffu, v, o);
        v = op ? (v + u) : fmaxf(v, u);
    }
    if (lane == 0) red[warp] = v;
    __syncthreads();
    int nw = (blockDim.x + 31) >> 5;
    if (warp == 0) {
        v = (lane < nw) ? red[lane] : (op ? 0.0f : -INFINITY);
        #pragma unroll
        for (int o = 16; o > 0; o >>= 1) {
            float u = __shfl_xor_sync(0xffffffffu, v, o);
            v = op ? (v + u) : fmaxf(v, u);
        }
        if (lane == 0) red[0] = v;
    }
    __syncthreads();
    float r = red[0];
    __syncthreads();
    return r;
}

// ============================================================================
// Mega fp16 wmma GEMM (one launch):
//   logits blocks: C = h1 @ out_W^T + out_b  -> half, via smem bias stage
//   dec2 blocks:   C = h1 @ [attn_W;cattn_W]^T -> float, direct store
// 256 threads (8 warps, 2x4), warp tile 64x32, reg prefetch double buffer.
// ============================================================================
__global__ void __launch_bounds__(256)
mega_fp16(const float* __restrict__ A,        // h1 [128,512]
          const float* __restrict__ Wout,     // [VV,512]
          const float* __restrict__ Wattn,    // [512,512]
          const float* __restrict__ Wcattn,   // [512,512]
          const float* __restrict__ out_b,    // [VV]
          __half* __restrict__ Clog,          // g_logits_h
          float* __restrict__ Cdec) {         // g_dec2
    extern __shared__ char dyn[];
    __half (*As)[128][40] = reinterpret_cast<__half (*)[128][40]>(dyn + MG_AS);
    __half (*Ws)[128][40] = reinterpret_cast<__half (*)[128][40]>(dyn + MG_WS);
    float* stage = reinterpret_cast<float*>(dyn + MG_STAGE);

    const int tid = threadIdx.x;
    const int wid = tid >> 5;
    const int lane = tid & 31;
    const int warp_m = wid >> 2;
    const int warp_n = wid & 3;
    const bool is_dec = (blockIdx.x >= NLOGIT);
    const int n0 = (is_dec ? (int)blockIdx.x - NLOGIT : (int)blockIdx.x) * 128;
    const int KT = 16;

    float4 ra[4], rw[4];

    auto wrow = [&](int nr) -> const float* {
        if (is_dec)
            return (nr < 512) ? Wattn + (size_t)nr * HH
                              : Wcattn + (size_t)(nr - 512) * HH;
        if (nr >= VV) nr = VV - 1;
        return Wout + (size_t)nr * HH;
    };

    auto ldg_stage = [&](int kt) {
        #pragma unroll
        for (int r = 0; r < 4; r++) {
            int f = tid + r * 256;
            int row = f >> 3, q = f & 7;
            ra[r] = *reinterpret_cast<const float4*>(
                A + (size_t)row * HH + kt * 32 + q * 4);
            rw[r] = *reinterpret_cast<const float4*>(
                wrow(n0 + row) + kt * 32 + q * 4);
        }
    };
    auto sts_stage = [&](int s) {
        #pragma unroll
        for (int r = 0; r < 4; r++) {
            int f = tid + r * 256;
            int row = f >> 3, q = f & 7;
            *reinterpret_cast<__half2*>(&As[s][row][q * 4]) =
                __floats2half2_rn(ra[r].x, ra[r].y);
            *reinterpret_cast<__half2*>(&As[s][row][q * 4 + 2]) =
                __floats2half2_rn(ra[r].z, ra[r].w);
            *reinterpret_cast<__half2*>(&Ws[s][row][q * 4]) =
                __floats2half2_rn(rw[r].x, rw[r].y);
            *reinterpret_cast<__half2*>(&Ws[s][row][q * 4 + 2]) =
                __floats2half2_rn(rw[r].z, rw[r].w);
        }
    };

    wmma::fragment<wmma::accumulator, 16, 16, 16, float> c[4][2];
    #pragma unroll
    for (int i = 0; i < 4; i++)
        #pragma unroll
        for (int j = 0; j < 2; j++) wmma::fill_fragment(c[i][j], 0.0f);

    ldg_stage(0);
    sts_stage(0);
    ldg_stage(1);
    __syncthreads();

    for (int kt = 0; kt < KT; kt++) {
        if (kt + 1 < KT) sts_stage((kt + 1) & 1);
        if (kt + 2 < KT) ldg_stage(kt + 2);

        const int s = kt & 1;
        #pragma unroll
        for (int k16 = 0; k16 < 32; k16 += 16) {
            wmma::fragment<wmma::matrix_a, 16, 16, 16, __half,
                           wmma::row_major> a[4];
            wmma::fragment<wmma::matrix_b, 16, 16, 16, __half,
                           wmma::col_major> b[2];
            #pragma unroll
            for (int mi = 0; mi < 4; mi++)
                wmma::load_matrix_sync(a[mi],
                    &As[s][warp_m * 64 + mi * 16][k16], 40);
            #pragma unroll
            for (int ni = 0; ni < 2; ni++)
                wmma::load_matrix_sync(b[ni],
                    &Ws[s][warp_n * 32 + ni * 16][k16], 40);
            #pragma unroll
            for (int mi = 0; mi < 4; mi++)
                #pragma unroll
                for (int ni = 0; ni < 2; ni++)
                    wmma::mma_sync(c[mi][ni], a[mi], b[ni], c[mi][ni]);
        }
        __syncthreads();
    }

    if (is_dec) {
        #pragma unroll
        for (int mi = 0; mi < 4; mi++)
            #pragma unroll
            for (int ni = 0; ni < 2; ni++)
                wmma::store_matrix_sync(
                    &Cdec[(size_t)(warp_m * 64 + mi * 16) * 1024 +
                          n0 + warp_n * 32 + ni * 16],
                    c[mi][ni], 1024, wmma::mem_row_major);
    } else {
        // bias-add epilogue via per-warp smem stage (ldm=20, mult of 4)
        float* st = stage + wid * 320;      // 16 x 20
        const int row = lane >> 1;
        const int cb = (lane & 1) * 8;
        #pragma unroll
        for (int mi = 0; mi < 4; mi++)
            #pragma unroll
            for (int ni = 0; ni < 2; ni++) {
                wmma::store_matrix_sync(st, c[mi][ni], 20, wmma::mem_row_major);
                __syncwarp();
                const int ro = warp_m * 64 + mi * 16;
                const int co = n0 + warp_n * 32 + ni * 16;
                __half* gp = Clog + (size_t)(ro + row) * LPAD + co + cb;
                #pragma unroll
                for (int j = 0; j < 8; j += 2) {
                    int nc0 = co + cb + j, nc1 = nc0 + 1;
                    float b0 = (nc0 < VV) ? out_b[nc0] : 0.0f;
                    float b1 = (nc1 < VV) ? out_b[nc1] : 0.0f;
                    *reinterpret_cast<__half2*>(gp + j) = __floats2half2_rn(
                        st[row * 20 + cb + j] + b0,
                        st[row * 20 + cb + j + 1] + b1);
                }
                __syncwarp();
            }
    }
}

// ============================================================================
// gates GEMM (tf32) with gate-interleaved W rows + fused LSTM epilogue.
// C col nv -> W row (nv&3)*512 + (nv>>2); block of 64 cols = 16 h x 4 gates.
// 256 threads, BN=64, 3-stage cp.async.
// ============================================================================
__global__ void __launch_bounds__(256)
gates_lstm(const float* __restrict__ A1, int lda1,    // embedding (gather)
           const float* __restrict__ A2, int lda2,    // h0
           const int* __restrict__ gather_idx,        // input
           const float* __restrict__ W1, int ldw1,    // W_ih
           const float* __restrict__ W2, int ldw2,    // W_hh
           int K1,
           const float* __restrict__ b_ih,
           const float* __restrict__ b_hh,
           const float* __restrict__ c0,
           float* __restrict__ h1_out,
           float* __restrict__ c1_out) {
    extern __shared__ float smem[];
    float* As = smem;                        // NSTG*128*ASTR
    float* Wsm = smem + NSTG * 128 * ASTR;   // NSTG*64*ASTR

    constexpr int BN = 64;
    const int tid = threadIdx.x;
    const int wid = tid >> 5;
    const int warp_m = wid >> 1;
    const int warp_n = wid & 1;
    const int n0 = blockIdx.x * BN;
    const int K = EE + HH;                   // 768
    const int KT = K >> 5;                   // 24

    const uint32_t as_base = (uint32_t)__cvta_generic_to_shared(As);
    const uint32_t ws_base = (uint32_t)__cvta_generic_to_shared(Wsm);

    auto issue_stage = [&](int kt, int s) {
        const int kk = kt << 5;
        #pragma unroll
        for (int r = 0; r < 4; r++) {
            int f = tid + r * 256;
            int row = f >> 3, kq = f & 7;
            int k = kk + kq * 4;
            const float* src;
            if (k < K1) {
                src = A1 + (size_t)gather_idx[row] * lda1 + k;
            } else {
                src = A2 + (size_t)row * lda2 + (k - K1);
            }
            cp_async16(as_base + (uint32_t)((s * 128 + row) * ASTR + kq * 4) * 4, src);
        }
        #pragma unroll
        for (int r = 0; r < 2; r++) {        // 64*8/256
            int f = tid + r * 256;
            int row = f >> 3, kq = f & 7;
            int k = kk + kq * 4;
            int nv = n0 + row;
            int wr = (nv & 3) * 512 + (nv >> 2);   // gate-interleave
            const float* src = (k < K1)
                ? W1 + (size_t)wr * ldw1 + k
                : W2 + (size_t)wr * ldw2 + (k - K1);
            cp_async16(ws_base + (uint32_t)((s * BN + row) * ASTR + kq * 4) * 4, src);
        }
        cp_commit();
    };

    wmma::fragment<wmma::accumulator, 16, 16, 8, float> c[2][2];
    #pragma unroll
    for (int i = 0; i < 2; i++)
        #pragma unroll
        for (int j = 0; j < 2; j++) wmma::fill_fragment(c[i][j], 0.0f);

    issue_stage(0, 0);
    issue_stage(1, 1);

    for (int kt = 0; kt < KT; kt++) {
        if (kt + 2 < KT) {
            issue_stage(kt + 2, (kt + 2) % NSTG);
            cp_wait<2>();
        } else if (kt + 1 < KT) {
            cp_wait<1>();
        } else {
            cp_wait<0>();
        }
        __syncthreads();

        const int s = kt % NSTG;
        const float* as = As + (size_t)s * 128 * ASTR;
        const float* ws = Wsm + (size_t)s * BN * ASTR;

        #pragma unroll
        for (int k8 = 0; k8 < 32; k8 += 8) {
            wmma::fragment<wmma::matrix_a, 16, 16, 8, wmma::precision::tf32,
                           wmma::row_major> a[2];
            wmma::fragment<wmma::matrix_b, 16, 16, 8, wmma::precision::tf32,
                           wmma::col_major> b[2];
            #pragma unroll
            for (int mi = 0; mi < 2; mi++)
                wmma::load_matrix_sync(a[mi],
                    as + (warp_m * 32 + mi * 16) * ASTR + k8, ASTR);
            #pragma unroll
            for (int ni = 0; ni < 2; ni++)
                wmma::load_matrix_sync(b[ni],
                    ws + (warp_n * 32 + ni * 16) * ASTR + k8, ASTR);
            #pragma unroll
            for (int mi = 0; mi < 2; mi++)
                #pragma unroll
                for (int ni = 0; ni < 2; ni++)
                    wmma::mma_sync(c[mi][ni], a[mi], b[ni], c[mi][ni]);
        }
        __syncthreads();
    }

    // ---- LSTM epilogue: stage C[128][64] in smem (stride 68), then pointwise
    float* Cs = smem;   // 128*68*4 = 34816 B, reuses pipeline smem
    #pragma unroll
    for (int mi = 0; mi < 2; mi++)
        #pragma unroll
        for (int ni = 0; ni < 2; ni++)
            wmma::store_matrix_sync(
                &Cs[(size_t)(warp_m * 32 + mi * 16) * 68 + warp_n * 32 + ni * 16],
                c[mi][ni], 68, wmma::mem_row_major);
    __syncthreads();

    const int h0b = n0 >> 2;   // first h of this block
    #pragma unroll
    for (int e = 0; e < 8; e++) {
        int f = tid + e * 256;          // 0..2047
        int brow = f >> 4;              // batch 0..127
        int hl = f & 15;                // local h 0..15
        int h = h0b + hl;
        const float* cr = &Cs[(size_t)brow * 68 + hl * 4];
        float gi = cr[0] + b_ih[h]            + b_hh[h];
        float gf = cr[1] + b_ih[HH + h]       + b_hh[HH + h];
        float gg = cr[2] + b_ih[2 * HH + h]   + b_hh[2 * HH + h];
        float go = cr[3] + b_ih[3 * HH + h]   + b_hh[3 * HH + h];
        float cc = sigmoidf_(gf) * c0[(size_t)brow * HH + h] +
                   sigmoidf_(gi) * tanhf(gg);
        float hh = sigmoidf_(go) * tanhf(cc);
        c1_out[(size_t)brow * HH + h] = cc;
        h1_out[(size_t)brow * HH + h] = hh;
    }
}

// ============================================================================
// Merged launch: flash attention (blocks [0, 2B)) + stats quarters (next 4B).
// ============================================================================
__global__ void __launch_bounds__(256)
flash_stats(const float* __restrict__ enc,
            const float* __restrict__ cenc,
            const float* __restrict__ attn_b,
            const float* __restrict__ cattn_b) {
    extern __shared__ float fs[];
    const int tid = threadIdx.x;

    if (blockIdx.x < 2 * BB) {
        const int aid = blockIdx.x >> 7;
        const int b = blockIdx.x & 127;
        const int T = aid ? TC : TT;
        const int NC = (T + FCH - 1) / FCH;
        const float* eb = (aid ? cenc : enc) + (size_t)b * T * HH;

        float* sdec = fs + FS_SDEC;
        float* sraw = fs + FS_SRAW;
        float* sc   = fs + FS_SC;
        float* swc  = fs + FS_SWC;
        float* chunk = fs + FS_CHUNK;
        const uint32_t ch_base = (uint32_t)__cvta_generic_to_shared(chunk);

        {
            const float* dec = g_dec2 + (size_t)b * 1024 + aid * HH;
            const float* bias = aid ? cattn_b : attn_b;
            sdec[tid] = dec[tid] + bias[tid];
            sdec[tid + 256] = dec[tid + 256] + bias[tid + 256];
        }

        auto issue_chunk = [&](int c) {
            const int s = c & 1;
            const int t0 = c * FCH;
            #pragma unroll
            for (int r = 0; r < 8; r++) {
                int f = tid + r * 256;
                int row = f >> 7;
                int c4 = f & 127;
                int t = t0 + row;
                if (t >= T) t = T - 1;
                cp_async16(ch_base + (uint32_t)(s * FCH * HH + row * HH + c4 * 4) * 4,
                           eb + (size_t)t * HH + c4 * 4);
            }
            cp_commit();
        };

        issue_chunk(0);
        __syncthreads();

        float acc0 = 0.0f, acc1 = 0.0f;
        float m = -INFINITY, ssum = 0.0f;
        const int warp = tid >> 5, lane = tid & 31;

        for (int c = 0; c < NC; c++) {
            if (c + 1 < NC) {
                issue_chunk(c + 1);
                cp_wait<1>();
            } else {
                cp_wait<0>();
            }
            __syncthreads();

            const float* ch = chunk + (c & 1) * FCH * HH;
            const int t0 = c * FCH;

            #pragma unroll
            for (int rr = 0; rr < 2; rr++) {
                int row = warp + rr * 8;
                int t = t0 + row;
                const float4* rp = reinterpret_cast<const float4*>(ch + row * HH);
                float s = 0.0f;
                #pragma unroll
                for (int q = 0; q < 4; q++) {
                    int f4 = lane + 32 * q;
                    float4 v = rp[f4];
                    s += v.x * sdec[f4 * 4 + 0] + v.y * sdec[f4 * 4 + 1] +
                         v.z * sdec[f4 * 4 + 2] + v.w * sdec[f4 * 4 + 3];
                }
                #pragma unroll
                for (int o = 16; o > 0; o >>= 1)
                    s += __shfl_xor_sync(0xffffffffu, s, o);
                if (lane == 0) {
                    sc[row] = (t < T) ? s : -INFINITY;
                    if (t < T) sraw[t] = s;
                }
            }
            __syncthreads();

            float mc = sc[0];
            #pragma unroll
            for (int t = 1; t < FCH; t++) mc = fmaxf(mc, sc[t]);
            float newm = fmaxf(m, mc);
            if (tid < FCH)
                swc[tid] = (sc[tid] == -INFINITY) ? 0.0f : __expf(sc[tid] - newm);
            __syncthreads();

            float f = (m == -INFINITY) ? 0.0f : __expf(m - newm);
            acc0 *= f;
            acc1 *= f;
            float wsum = 0.0f;
            #pragma unroll
            for (int t = 0; t < FCH; t++) {
                float w = swc[t];
                wsum += w;
                acc0 += w * ch[t * HH + tid];
                acc1 += w * ch[t * HH + tid + 256];
            }
            ssum = ssum * f + wsum;
            m = newm;
            __syncthreads();
        }

        float inv = 1.0f / ssum;
        float* dst = aid ? g_cctx : g_context;
        dst[(size_t)b * HH + tid] = acc0 * inv;
        dst[(size_t)b * HH + tid + 256] = acc1 * inv;

        if (aid == 1) {
            if (tid < T) g_nscores[b][tid] = __expf(sraw[tid] - m) * inv;
        }
    } else {
        // ---- stats quarter: online (m, s) over half logits (bias included) ----
        const int idx = blockIdx.x - 2 * BB;
        const int q = idx & 3;
        const int b = idx >> 2;
        const int v0 = q * QSTAT;
        const int v1 = (q == 3) ? VV : v0 + QSTAT;
        const __half* lg = g_logits_h + (size_t)b * LPAD;
        float* red = fs;

        float m = -INFINITY, s = 0.0f;
        for (int v = v0 + tid; v < v1; v += 256) {
            float x = __half2float(lg[v]);
            if (x > m) {
                s = s * __expf(m - x) + 1.0f;
                m = x;
            } else {
                s += __expf(x - m);
            }
        }
        float M = block_reduce(m, red, 0);
        s = (m == -INFINITY) ? 0.0f : s * __expf(m - M);
        float S = block_reduce(s, red, 1);
        if (tid == 0) {
            g_part[b][q][0] = M;
            g_part[b][q][1] = S;
        }
    }
}

// ============================================================================
// write: quarter-V-range prob + copy + log, with FUSED p_gen.
// grid (4, B), 256 threads.
// ============================================================================
__global__ void __launch_bounds__(256)
write_kernel(const int* __restrict__ context_input,
             const float* __restrict__ h1,
             const float* __restrict__ embedding,
             const int* __restrict__ input,
             const float* __restrict__ gen_W,
             const float* __restrict__ gen_b,
             const float* __restrict__ sig_b,
             float* __restrict__ out) {
    extern __shared__ float copyv[];     // QWR floats + 32 red
    float* red = copyv + QWR;
    const int qq = blockIdx.x;
    const int b = blockIdx.y;
    const int tid = threadIdx.x;
    const int base = qq * QWR;
    const int len = (base + QWR <= VEXT) ? QWR : (VEXT - base);

    // ---- fused p_gen ----
    float s = 0.0f;
    for (int k = tid; k < HH; k += 256) {
        s += g_context[b * HH + k] * gen_W[k];
        s += g_cctx[b * HH + k] * gen_W[HH + k];
        s += h1[(size_t)b * HH + k] * gen_W[2 * HH + k];
    }
    {
        const float* emb = embedding + (size_t)input[b] * EE;
        for (int k = tid; k < EE; k += 256) s += emb[k] * gen_W[3 * HH + k];
    }
    s = block_reduce(s, red, 1);
    float cnt = 0.0f;
    for (int t = tid; t < TC; t += 256)
        cnt += (context_input[(size_t)b * TC + t] > 0) ? 1.0f : 0.0f;
    cnt = block_reduce(cnt, red, 1);
    float pg = sigmoidf_(s + gen_b[0] + sig_b[0]);
    if (cnt == 0.0f) pg = 1.0f;

    // ---- softmax scale from stats partials ----
    float M = fmaxf(fmaxf(g_part[b][0][0], g_part[b][1][0]),
                    fmaxf(g_part[b][2][0], g_part[b][3][0]));
    float S = g_part[b][0][1] * __expf(g_part[b][0][0] - M)
            + g_part[b][1][1] * __expf(g_part[b][1][0] - M)
            + g_part[b][2][1] * __expf(g_part[b][2][0] - M)
            + g_part[b][3][1] * __expf(g_part[b][3][0] - M);
    const float scale = pg / S;

    for (int v = tid; v < len; v += 256) copyv[v] = 0.0f;
    __syncthreads();

    if (tid < TC) {
        int idx = context_input[(size_t)b * TC + tid];
        if (idx >= base && idx < base + len) {
            float w = (1.0f - pg) * g_nscores[b][tid];
            atomicAdd(&copyv[idx - base], w);
        }
    }
    __syncthreads();

    const __half* lg = g_logits_h + (size_t)b * LPAD;
    float* row = out + (size_t)b * VEXT;

    const int vend = (base + len < VV) ? (base + len) : VV;
    for (int v = base + tid; v < vend; v += 256) {
        float p = __expf(__half2float(lg[v]) - M) * scale + copyv[v - base];
        row[v] = __logf(fmaxf(p, 1e-10f));
    }
    for (int v = (VV > base ? VV : base) + tid; v < base + len; v += 256)
        row[v] = __logf(fmaxf(copyv[v - base], 1e-10f));
}

// ---------------- launcher ----------------
extern "C" void kernel_launch(void* const* d_in, const int* in_sizes, int n_in,
                              void* d_out, int out_size) {
    const int*   input    = (const int*)  d_in[0];
    const float* h0       = (const float*)d_in[1];
    const float* c0       = (const float*)d_in[2];
    const float* enc      = (const float*)d_in[3];
    const float* cenc     = (const float*)d_in[4];
    const int*   ctx_in   = (const int*)  d_in[5];
    const float* embedding= (const float*)d_in[6];
    const float* W_ih     = (const float*)d_in[7];
    const float* W_hh     = (const float*)d_in[8];
    const float* b_ih     = (const float*)d_in[9];
    const float* b_hh     = (const float*)d_in[10];
    const float* attn_W   = (const float*)d_in[11];
    const float* attn_b   = (const float*)d_in[12];
    const float* cattn_W  = (const float*)d_in[13];
    const float* cattn_b  = (const float*)d_in[14];
    const float* gen_W    = (const float*)d_in[15];
    const float* gen_b    = (const float*)d_in[16];
    const float* sig_b    = (const float*)d_in[17];
    const float* out_W    = (const float*)d_in[18];
    const float* out_b    = (const float*)d_in[19];

    float* out = (float*)d_out;
    float* logp   = out;
    float* h1_out = out + (size_t)BB * VEXT;
    float* c1_out = h1_out + (size_t)BB * HH;

    float*  d_dec2;    cudaGetSymbolAddress((void**)&d_dec2,    g_dec2);
    __half* d_logits;  cudaGetSymbolAddress((void**)&d_logits,  g_logits_h);

    const int SMEM_GL   = NSTG * (128 + 64) * ASTR * 4;  // 82944
    const int SMEM_FL   = FS_TOTAL * 4;                  // 68736
    const int SMEM_WRITE = (QWR + 32) * 4;               // ~50180
    cudaFuncSetAttribute(gates_lstm,
        cudaFuncAttributeMaxDynamicSharedMemorySize, SMEM_GL);
    cudaFuncSetAttribute(mega_fp16,
        cudaFuncAttributeMaxDynamicSharedMemorySize, MG_TOTAL);
    cudaFuncSetAttribute(flash_stats,
        cudaFuncAttributeMaxDynamicSharedMemorySize, SMEM_FL);
    cudaFuncSetAttribute(write_kernel,
        cudaFuncAttributeMaxDynamicSharedMemorySize, SMEM_WRITE);

    // 1) fused gates GEMM + LSTM -> h1, c1 (into d_out tail)
    gates_lstm<<<H4 / 64, 256, SMEM_GL>>>(
        embedding, EE, h0, HH, input,
        W_ih, EE, W_hh, HH, EE,
        b_ih, b_hh, c0, h1_out, c1_out);

    // 2) mega fp16 GEMM: logits+bias (half out) + dec2
    mega_fp16<<<NLOGIT + NDEC, 256, MG_TOTAL>>>(
        h1_out, out_W, attn_W, cattn_W, out_b, d_logits, d_dec2);

    // 3) flash attention (enc read once) + softmax stats partials
    flash_stats<<<2 * BB + 4 * BB, 256, SMEM_FL>>>(
        enc, cenc, attn_b, cattn_b);

    // 4) fused p_gen + prob + copy-scatter + log, quarter split [ncu slot]
    write_kernel<<<dim3(4, BB), 256, SMEM_WRITE>>>(
        ctx_in, h1_out, embedding, input, gen_W, gen_b, sig_b, logp);
}

// round 15
// speedup vs baseline: 1.1190x; 1.1190x over previous
#include <cuda_runtime.h>
#include <cuda_fp16.h>
#include <mma.h>
#include <math.h>
#include <cstdint>

using namespace nvcuda;

// ---------------- problem constants ----------------
#define BB   128
#define TT   256
#define TC   200
#define EE   256
#define HH   512
#define H4   2048
#define VV   50000
#define MAX_OOV 50
#define VEXT 50050
#define LPAD 50176   // padded logits row stride

#define QSTAT 12500  // stats partial range (VV/4)
#define NWR   8      // write splits per row
#define QWR   6257   // write range (ceil VEXT/8)

#define ASTR 36      // tf32 gemm smem row stride (floats)
#define NSTG 3       // tf32 gemm cp.async stages

#define NLOGIT (LPAD / 128)        // 392 logits blocks
#define NDEC   8                   // dec2 blocks (N=1024)

#define FCH 16                     // flash-attn chunk rows
#define FS_SDEC  0
#define FS_SRAW  512
#define FS_SC    (512 + 256)
#define FS_SWC   (512 + 256 + 16)
#define FS_CHUNK (512 + 256 + 32)
#define FS_TOTAL (FS_CHUNK + 2 * FCH * HH)   // 17184 floats = 68736 B

#define LOGMIN (-23.02585093f)     // log(1e-10)

// ---------------- scratch (device globals; no allocation) ----------------
__device__ float g_dec2[BB * 1024];        // [dec | cdec] per row
__device__ float g_context[BB * HH];
__device__ float g_cctx[BB * HH];
__device__ float g_nscores[BB][TT];        // normalized cscores (attn 1)
__device__ float g_part[BB][4][2];         // per-quarter online {m, s}
__device__ __half g_logits_h[BB * LPAD];   // fp16 logits (12.8 MB)

__device__ __forceinline__ float sigmoidf_(float x) {
    return 1.0f / (1.0f + __expf(-x));
}

// ---------------- cp.async helpers ----------------
__device__ __forceinline__ void cp_async16(uint32_t dst, const void* src) {
    asm volatile("cp.async.cg.shared.global [%0], [%1], 16;\n" :: "r"(dst), "l"(src));
}
__device__ __forceinline__ void cp_commit() {
    asm volatile("cp.async.commit_group;\n" ::);
}
template <int N>
__device__ __forceinline__ void cp_wait() {
    asm volatile("cp.async.wait_group %0;\n" :: "n"(N));
}

// block reduce: op 0 = max, 1 = sum (blockDim <= 1024)
__device__ __forceinline__ float block_reduce(float v, float* red, int op) {
    int lane = threadIdx.x & 31, warp = threadIdx.x >> 5;
    #pragma unroll
    for (int o = 16; o > 0; o >>= 1) {
        float u = __shfl_xor_sync(0xffffffffu, v, o);
        v = op ? (v + u) : fmaxf(v, u);
    }
    if (lane == 0) red[warp] = v;
    __syncthreads();
    int nw = (blockDim.x + 31) >> 5;
    if (warp == 0) {
        v = (lane < nw) ? red[lane] : (op ? 0.0f : -INFINITY);
        #pragma unroll
        for (int o = 16; o > 0; o >>= 1) {
            float u = __shfl_xor_sync(0xffffffffu, v, o);
            v = op ? (v + u) : fmaxf(v, u);
        }
        if (lane == 0) red[0] = v;
    }
    __syncthreads();
    float r = red[0];
    __syncthreads();
    return r;
}

// ============================================================================
// Mega fp16 wmma GEMM (one launch):
//   logits blocks: half output via fragment convert (round-12 style, no bias)
//   dec2 blocks:   float output
// ============================================================================
__global__ void __launch_bounds__(256)
mega_fp16(const float* __restrict__ A,        // h1 [128,512]
          const float* __restrict__ Wout,     // [VV,512]
          const float* __restrict__ Wattn,    // [512,512]
          const float* __restrict__ Wcattn,   // [512,512]
          __half* __restrict__ Clog,          // g_logits_h
          float* __restrict__ Cdec) {         // g_dec2
    __shared__ __half As[2][128][40];
    __shared__ __half Ws[2][128][40];

    const int tid = threadIdx.x;
    const int wid = tid >> 5;
    const int warp_m = wid >> 2;
    const int warp_n = wid & 3;
    const bool is_dec = (blockIdx.x >= NLOGIT);
    const int n0 = (is_dec ? (int)blockIdx.x - NLOGIT : (int)blockIdx.x) * 128;
    const int KT = 16;

    float4 ra[4], rw[4];

    auto wrow = [&](int nr) -> const float* {
        if (is_dec)
            return (nr < 512) ? Wattn + (size_t)nr * HH
                              : Wcattn + (size_t)(nr - 512) * HH;
        if (nr >= VV) nr = VV - 1;
        return Wout + (size_t)nr * HH;
    };

    auto ldg_stage = [&](int kt) {
        #pragma unroll
        for (int r = 0; r < 4; r++) {
            int f = tid + r * 256;
            int row = f >> 3, q = f & 7;
            ra[r] = *reinterpret_cast<const float4*>(
                A + (size_t)row * HH + kt * 32 + q * 4);
            rw[r] = *reinterpret_cast<const float4*>(
                wrow(n0 + row) + kt * 32 + q * 4);
        }
    };
    auto sts_stage = [&](int s) {
        #pragma unroll
        for (int r = 0; r < 4; r++) {
            int f = tid + r * 256;
            int row = f >> 3, q = f & 7;
            *reinterpret_cast<__half2*>(&As[s][row][q * 4]) =
                __floats2half2_rn(ra[r].x, ra[r].y);
            *reinterpret_cast<__half2*>(&As[s][row][q * 4 + 2]) =
                __floats2half2_rn(ra[r].z, ra[r].w);
            *reinterpret_cast<__half2*>(&Ws[s][row][q * 4]) =
                __floats2half2_rn(rw[r].x, rw[r].y);
            *reinterpret_cast<__half2*>(&Ws[s][row][q * 4 + 2]) =
                __floats2half2_rn(rw[r].z, rw[r].w);
        }
    };

    wmma::fragment<wmma::accumulator, 16, 16, 16, float> c[4][2];
    #pragma unroll
    for (int i = 0; i < 4; i++)
        #pragma unroll
        for (int j = 0; j < 2; j++) wmma::fill_fragment(c[i][j], 0.0f);

    ldg_stage(0);
    sts_stage(0);
    ldg_stage(1);
    __syncthreads();

    for (int kt = 0; kt < KT; kt++) {
        if (kt + 1 < KT) sts_stage((kt + 1) & 1);
        if (kt + 2 < KT) ldg_stage(kt + 2);

        const int s = kt & 1;
        #pragma unroll
        for (int k16 = 0; k16 < 32; k16 += 16) {
            wmma::fragment<wmma::matrix_a, 16, 16, 16, __half,
                           wmma::row_major> a[4];
            wmma::fragment<wmma::matrix_b, 16, 16, 16, __half,
                           wmma::col_major> b[2];
            #pragma unroll
            for (int mi = 0; mi < 4; mi++)
                wmma::load_matrix_sync(a[mi],
                    &As[s][warp_m * 64 + mi * 16][k16], 40);
            #pragma unroll
            for (int ni = 0; ni < 2; ni++)
                wmma::load_matrix_sync(b[ni],
                    &Ws[s][warp_n * 32 + ni * 16][k16], 40);
            #pragma unroll
            for (int mi = 0; mi < 4; mi++)
                #pragma unroll
                for (int ni = 0; ni < 2; ni++)
                    wmma::mma_sync(c[mi][ni], a[mi], b[ni], c[mi][ni]);
        }
        __syncthreads();
    }

    #pragma unroll
    for (int mi = 0; mi < 4; mi++)
        #pragma unroll
        for (int ni = 0; ni < 2; ni++) {
            const int ro = warp_m * 64 + mi * 16;
            const int co = n0 + warp_n * 32 + ni * 16;
            if (is_dec) {
                wmma::store_matrix_sync(&Cdec[(size_t)ro * 1024 + co],
                                        c[mi][ni], 1024, wmma::mem_row_major);
            } else {
                wmma::fragment<wmma::accumulator, 16, 16, 16, __half> hc;
                #pragma unroll
                for (int e = 0; e < hc.num_elements; e++)
                    hc.x[e] = __float2half(c[mi][ni].x[e]);
                wmma::store_matrix_sync(&Clog[(size_t)ro * LPAD + co],
                                        hc, LPAD, wmma::mem_row_major);
            }
        }
}

// ============================================================================
// gates GEMM (tf32) with gate-interleaved W rows + fused LSTM epilogue.
// ============================================================================
__global__ void __launch_bounds__(256)
gates_lstm(const float* __restrict__ A1, int lda1,    // embedding (gather)
           const float* __restrict__ A2, int lda2,    // h0
           const int* __restrict__ gather_idx,        // input
           const float* __restrict__ W1, int ldw1,    // W_ih
           const float* __restrict__ W2, int ldw2,    // W_hh
           int K1,
           const float* __restrict__ b_ih,
           const float* __restrict__ b_hh,
           const float* __restrict__ c0,
           float* __restrict__ h1_out,
           float* __restrict__ c1_out) {
    extern __shared__ float smem[];
    float* As = smem;                        // NSTG*128*ASTR
    float* Wsm = smem + NSTG * 128 * ASTR;   // NSTG*64*ASTR

    constexpr int BN = 64;
    const int tid = threadIdx.x;
    const int wid = tid >> 5;
    const int warp_m = wid >> 1;
    const int warp_n = wid & 1;
    const int n0 = blockIdx.x * BN;
    const int K = EE + HH;                   // 768
    const int KT = K >> 5;                   // 24

    const uint32_t as_base = (uint32_t)__cvta_generic_to_shared(As);
    const uint32_t ws_base = (uint32_t)__cvta_generic_to_shared(Wsm);

    auto issue_stage = [&](int kt, int s) {
        const int kk = kt << 5;
        #pragma unroll
        for (int r = 0; r < 4; r++) {
            int f = tid + r * 256;
            int row = f >> 3, kq = f & 7;
            int k = kk + kq * 4;
            const float* src;
            if (k < K1) {
                src = A1 + (size_t)gather_idx[row] * lda1 + k;
            } else {
                src = A2 + (size_t)row * lda2 + (k - K1);
            }
            cp_async16(as_base + (uint32_t)((s * 128 + row) * ASTR + kq * 4) * 4, src);
        }
        #pragma unroll
        for (int r = 0; r < 2; r++) {
            int f = tid + r * 256;
            int row = f >> 3, kq = f & 7;
            int k = kk + kq * 4;
            int nv = n0 + row;
            int wr = (nv & 3) * 512 + (nv >> 2);   // gate-interleave
            const float* src = (k < K1)
                ? W1 + (size_t)wr * ldw1 + k
                : W2 + (size_t)wr * ldw2 + (k - K1);
            cp_async16(ws_base + (uint32_t)((s * BN + row) * ASTR + kq * 4) * 4, src);
        }
        cp_commit();
    };

    wmma::fragment<wmma::accumulator, 16, 16, 8, float> c[2][2];
    #pragma unroll
    for (int i = 0; i < 2; i++)
        #pragma unroll
        for (int j = 0; j < 2; j++) wmma::fill_fragment(c[i][j], 0.0f);

    issue_stage(0, 0);
    issue_stage(1, 1);

    for (int kt = 0; kt < KT; kt++) {
        if (kt + 2 < KT) {
            issue_stage(kt + 2, (kt + 2) % NSTG);
            cp_wait<2>();
        } else if (kt + 1 < KT) {
            cp_wait<1>();
        } else {
            cp_wait<0>();
        }
        __syncthreads();

        const int s = kt % NSTG;
        const float* as = As + (size_t)s * 128 * ASTR;
        const float* ws = Wsm + (size_t)s * BN * ASTR;

        #pragma unroll
        for (int k8 = 0; k8 < 32; k8 += 8) {
            wmma::fragment<wmma::matrix_a, 16, 16, 8, wmma::precision::tf32,
                           wmma::row_major> a[2];
            wmma::fragment<wmma::matrix_b, 16, 16, 8, wmma::precision::tf32,
                           wmma::col_major> b[2];
            #pragma unroll
            for (int mi = 0; mi < 2; mi++)
                wmma::load_matrix_sync(a[mi],
                    as + (warp_m * 32 + mi * 16) * ASTR + k8, ASTR);
            #pragma unroll
            for (int ni = 0; ni < 2; ni++)
                wmma::load_matrix_sync(b[ni],
                    ws + (warp_n * 32 + ni * 16) * ASTR + k8, ASTR);
            #pragma unroll
            for (int mi = 0; mi < 2; mi++)
                #pragma unroll
                for (int ni = 0; ni < 2; ni++)
                    wmma::mma_sync(c[mi][ni], a[mi], b[ni], c[mi][ni]);
        }
        __syncthreads();
    }

    // ---- LSTM epilogue: stage C[128][64] in smem (stride 68), then pointwise
    float* Cs = smem;
    #pragma unroll
    for (int mi = 0; mi < 2; mi++)
        #pragma unroll
        for (int ni = 0; ni < 2; ni++)
            wmma::store_matrix_sync(
                &Cs[(size_t)(warp_m * 32 + mi * 16) * 68 + warp_n * 32 + ni * 16],
                c[mi][ni], 68, wmma::mem_row_major);
    __syncthreads();

    const int h0b = n0 >> 2;
    #pragma unroll
    for (int e = 0; e < 8; e++) {
        int f = tid + e * 256;
        int brow = f >> 4;
        int hl = f & 15;
        int h = h0b + hl;
        const float* cr = &Cs[(size_t)brow * 68 + hl * 4];
        float gi = cr[0] + b_ih[h]            + b_hh[h];
        float gf = cr[1] + b_ih[HH + h]       + b_hh[HH + h];
        float gg = cr[2] + b_ih[2 * HH + h]   + b_hh[2 * HH + h];
        float go = cr[3] + b_ih[3 * HH + h]   + b_hh[3 * HH + h];
        float cc = sigmoidf_(gf) * c0[(size_t)brow * HH + h] +
                   sigmoidf_(gi) * tanhf(gg);
        float hh = sigmoidf_(go) * tanhf(cc);
        c1_out[(size_t)brow * HH + h] = cc;
        h1_out[(size_t)brow * HH + h] = hh;
    }
}

// ============================================================================
// Merged launch: flash attention (blocks [0, 2B)) + stats quarters (next 4B).
// ============================================================================
__global__ void __launch_bounds__(256)
flash_stats(const float* __restrict__ enc,
            const float* __restrict__ cenc,
            const float* __restrict__ attn_b,
            const float* __restrict__ cattn_b,
            const float* __restrict__ out_b) {
    extern __shared__ float fs[];
    const int tid = threadIdx.x;

    if (blockIdx.x < 2 * BB) {
        const int aid = blockIdx.x >> 7;
        const int b = blockIdx.x & 127;
        const int T = aid ? TC : TT;
        const int NC = (T + FCH - 1) / FCH;
        const float* eb = (aid ? cenc : enc) + (size_t)b * T * HH;

        float* sdec = fs + FS_SDEC;
        float* sraw = fs + FS_SRAW;
        float* sc   = fs + FS_SC;
        float* swc  = fs + FS_SWC;
        float* chunk = fs + FS_CHUNK;
        const uint32_t ch_base = (uint32_t)__cvta_generic_to_shared(chunk);

        {
            const float* dec = g_dec2 + (size_t)b * 1024 + aid * HH;
            const float* bias = aid ? cattn_b : attn_b;
            sdec[tid] = dec[tid] + bias[tid];
            sdec[tid + 256] = dec[tid + 256] + bias[tid + 256];
        }

        auto issue_chunk = [&](int c) {
            const int s = c & 1;
            const int t0 = c * FCH;
            #pragma unroll
            for (int r = 0; r < 8; r++) {
                int f = tid + r * 256;
                int row = f >> 7;
                int c4 = f & 127;
                int t = t0 + row;
                if (t >= T) t = T - 1;
                cp_async16(ch_base + (uint32_t)(s * FCH * HH + row * HH + c4 * 4) * 4,
                           eb + (size_t)t * HH + c4 * 4);
            }
            cp_commit();
        };

        issue_chunk(0);
        __syncthreads();

        float acc0 = 0.0f, acc1 = 0.0f;
        float m = -INFINITY, ssum = 0.0f;
        const int warp = tid >> 5, lane = tid & 31;

        for (int c = 0; c < NC; c++) {
            if (c + 1 < NC) {
                issue_chunk(c + 1);
                cp_wait<1>();
            } else {
                cp_wait<0>();
            }
            __syncthreads();

            const float* ch = chunk + (c & 1) * FCH * HH;
            const int t0 = c * FCH;

            #pragma unroll
            for (int rr = 0; rr < 2; rr++) {
                int row = warp + rr * 8;
                int t = t0 + row;
                const float4* rp = reinterpret_cast<const float4*>(ch + row * HH);
                float s = 0.0f;
                #pragma unroll
                for (int q = 0; q < 4; q++) {
                    int f4 = lane + 32 * q;
                    float4 v = rp[f4];
                    s += v.x * sdec[f4 * 4 + 0] + v.y * sdec[f4 * 4 + 1] +
                         v.z * sdec[f4 * 4 + 2] + v.w * sdec[f4 * 4 + 3];
                }
                #pragma unroll
                for (int o = 16; o > 0; o >>= 1)
                    s += __shfl_xor_sync(0xffffffffu, s, o);
                if (lane == 0) {
                    sc[row] = (t < T) ? s : -INFINITY;
                    if (t < T) sraw[t] = s;
                }
            }
            __syncthreads();

            float mc = sc[0];
            #pragma unroll
            for (int t = 1; t < FCH; t++) mc = fmaxf(mc, sc[t]);
            float newm = fmaxf(m, mc);
            if (tid < FCH)
                swc[tid] = (sc[tid] == -INFINITY) ? 0.0f : __expf(sc[tid] - newm);
            __syncthreads();

            float f = (m == -INFINITY) ? 0.0f : __expf(m - newm);
            acc0 *= f;
            acc1 *= f;
            float wsum = 0.0f;
            #pragma unroll
            for (int t = 0; t < FCH; t++) {
                float w = swc[t];
                wsum += w;
                acc0 += w * ch[t * HH + tid];
                acc1 += w * ch[t * HH + tid + 256];
            }
            ssum = ssum * f + wsum;
            m = newm;
            __syncthreads();
        }

        float inv = 1.0f / ssum;
        float* dst = aid ? g_cctx : g_context;
        dst[(size_t)b * HH + tid] = acc0 * inv;
        dst[(size_t)b * HH + tid + 256] = acc1 * inv;

        if (aid == 1) {
            if (tid < T) g_nscores[b][tid] = __expf(sraw[tid] - m) * inv;
        }
    } else {
        // ---- stats quarter: online (m, s) over half logits + out_b ----
        const int idx = blockIdx.x - 2 * BB;
        const int q = idx & 3;
        const int b = idx >> 2;
        const int v0 = q * QSTAT;
        const int v1 = (q == 3) ? VV : v0 + QSTAT;
        const __half* lg = g_logits_h + (size_t)b * LPAD;
        float* red = fs;

        float m = -INFINITY, s = 0.0f;
        for (int v = v0 + tid; v < v1; v += 256) {
            float x = __half2float(lg[v]) + out_b[v];
            if (x > m) {
                s = s * __expf(m - x) + 1.0f;
                m = x;
            } else {
                s += __expf(x - m);
            }
        }
        float M = block_reduce(m, red, 0);
        s = (m == -INFINITY) ? 0.0f : s * __expf(m - M);
        float S = block_reduce(s, red, 1);
        if (tid == 0) {
            g_part[b][q][0] = M;
            g_part[b][q][1] = S;
        }
    }
}

// ============================================================================
// write: 1/8-V-range prob + copy + log, FUSED p_gen, LINEAR-LOG fast path.
// For copyv==0 (vast majority): logp = max(x - M + log(scale), log(1e-10)) —
// no exp/log needed. Only scattered indices take the exp->add->log path.
// grid (NWR, B), 256 threads.
// ============================================================================
__global__ void __launch_bounds__(256)
write_kernel(const float* __restrict__ out_b,
             const int* __restrict__ context_input,
             const float* __restrict__ h1,
             const float* __restrict__ embedding,
             const int* __restrict__ input,
             const float* __restrict__ gen_W,
             const float* __restrict__ gen_b,
             const float* __restrict__ sig_b,
             float* __restrict__ out) {
    extern __shared__ float copyv[];     // QWR floats + 32 red
    float* red = copyv + QWR;
    const int qq = blockIdx.x;
    const int b = blockIdx.y;
    const int tid = threadIdx.x;
    const int base = qq * QWR;
    const int len = (base + QWR <= VEXT) ? QWR : (VEXT - base);

    // ---- fused p_gen ----
    float s = 0.0f;
    for (int k = tid; k < HH; k += 256) {
        s += g_context[b * HH + k] * gen_W[k];
        s += g_cctx[b * HH + k] * gen_W[HH + k];
        s += h1[(size_t)b * HH + k] * gen_W[2 * HH + k];
    }
    {
        const float* emb = embedding + (size_t)input[b] * EE;
        for (int k = tid; k < EE; k += 256) s += emb[k] * gen_W[3 * HH + k];
    }
    s = block_reduce(s, red, 1);
    float cnt = 0.0f;
    for (int t = tid; t < TC; t += 256)
        cnt += (context_input[(size_t)b * TC + t] > 0) ? 1.0f : 0.0f;
    cnt = block_reduce(cnt, red, 1);
    float pg = sigmoidf_(s + gen_b[0] + sig_b[0]);
    if (cnt == 0.0f) pg = 1.0f;

    // ---- softmax scale from stats partials ----
    float M = fmaxf(fmaxf(g_part[b][0][0], g_part[b][1][0]),
                    fmaxf(g_part[b][2][0], g_part[b][3][0]));
    float S = g_part[b][0][1] * __expf(g_part[b][0][0] - M)
            + g_part[b][1][1] * __expf(g_part[b][1][0] - M)
            + g_part[b][2][1] * __expf(g_part[b][2][0] - M)
            + g_part[b][3][1] * __expf(g_part[b][3][0] - M);
    const float scale = pg / S;
    const float lsc = __logf(scale);

    for (int v = tid; v < len; v += 256) copyv[v] = 0.0f;
    __syncthreads();

    if (tid < TC) {
        int idx = context_input[(size_t)b * TC + tid];
        if (idx >= base && idx < base + len) {
            float w = (1.0f - pg) * g_nscores[b][tid];
            atomicAdd(&copyv[idx - base], w);
        }
    }
    __syncthreads();

    const __half* lg = g_logits_h + (size_t)b * LPAD;
    float* row = out + (size_t)b * VEXT;

    const int vend = (base + len < VV) ? (base + len) : VV;
    for (int v = base + tid; v < vend; v += 256) {
        float x = __half2float(lg[v]) + out_b[v];
        float cv = copyv[v - base];
        float r;
        if (cv > 0.0f) {
            float p = __expf(x - M) * scale + cv;
            r = __logf(fmaxf(p, 1e-10f));
        } else {
            r = fmaxf(x - M + lsc, LOGMIN);
        }
        row[v] = r;
    }
    // OOV tail (copy-only region)
    for (int v = (VV > base ? VV : base) + tid; v < base + len; v += 256)
        row[v] = __logf(fmaxf(copyv[v - base], 1e-10f));
}

// ---------------- launcher ----------------
extern "C" void kernel_launch(void* const* d_in, const int* in_sizes, int n_in,
                              void* d_out, int out_size) {
    const int*   input    = (const int*)  d_in[0];
    const float* h0       = (const float*)d_in[1];
    const float* c0       = (const float*)d_in[2];
    const float* enc      = (const float*)d_in[3];
    const float* cenc     = (const float*)d_in[4];
    const int*   ctx_in   = (const int*)  d_in[5];
    const float* embedding= (const float*)d_in[6];
    const float* W_ih     = (const float*)d_in[7];
    const float* W_hh     = (const float*)d_in[8];
    const float* b_ih     = (const float*)d_in[9];
    const float* b_hh     = (const float*)d_in[10];
    const float* attn_W   = (const float*)d_in[11];
    const float* attn_b   = (const float*)d_in[12];
    const float* cattn_W  = (const float*)d_in[13];
    const float* cattn_b  = (const float*)d_in[14];
    const float* gen_W    = (const float*)d_in[15];
    const float* gen_b    = (const float*)d_in[16];
    const float* sig_b    = (const float*)d_in[17];
    const float* out_W    = (const float*)d_in[18];
    const float* out_b    = (const float*)d_in[19];

    float* out = (float*)d_out;
    float* logp   = out;
    float* h1_out = out + (size_t)BB * VEXT;
    float* c1_out = h1_out + (size_t)BB * HH;

    float*  d_dec2;    cudaGetSymbolAddress((void**)&d_dec2,    g_dec2);
    __half* d_logits;  cudaGetSymbolAddress((void**)&d_logits,  g_logits_h);

    const int SMEM_GL   = NSTG * (128 + 64) * ASTR * 4;  // 82944
    const int SMEM_FL   = FS_TOTAL * 4;                  // 68736
    const int SMEM_WRITE = (QWR + 32) * 4;               // 25156
    cudaFuncSetAttribute(gates_lstm,
        cudaFuncAttributeMaxDynamicSharedMemorySize, SMEM_GL);
    cudaFuncSetAttribute(flash_stats,
        cudaFuncAttributeMaxDynamicSharedMemorySize, SMEM_FL);
    cudaFuncSetAttribute(write_kernel,
        cudaFuncAttributeMaxDynamicSharedMemorySize, SMEM_WRITE);

    // 1) fused gates GEMM + LSTM -> h1, c1 (into d_out tail)
    gates_lstm<<<H4 / 64, 256, SMEM_GL>>>(
        embedding, EE, h0, HH, input,
        W_ih, EE, W_hh, HH, EE,
        b_ih, b_hh, c0, h1_out, c1_out);

    // 2) mega fp16 GEMM: logits (half out) + dec2
    mega_fp16<<<NLOGIT + NDEC, 256>>>(h1_out, out_W, attn_W, cattn_W,
                                      d_logits, d_dec2);

    // 3) flash attention (enc read once) + softmax stats partials
    flash_stats<<<2 * BB + 4 * BB, 256, SMEM_FL>>>(
        enc, cenc, attn_b, cattn_b, out_b);

    // 4) fused p_gen + linear-log prob + copy-scatter, 1/8 split [ncu slot]
    write_kernel<<<dim3(NWR, BB), 256, SMEM_WRITE>>>(
        out_b, ctx_in, h1_out, embedding, input, gen_W, gen_b, sig_b, logp);
}